// round 9
// baseline (speedup 1.0000x reference)
#include <cuda_runtime.h>
#include <cuda_bf16.h>
#include <cstdint>

// ---------------------------------------------------------------------------
// Problem constants
// ---------------------------------------------------------------------------
#define N_ATOMS   100000
#define N_BONDS   200000
#define MAX_NB    6
#define ATOM_FDIM 133
#define BOND_FDIM 147
#define HIDDEN    300
#define N_MOLS_C  5000
#define CAT_DIM   433          // ATOM_FDIM + HIDDEN

// Padded dims
#define KP_BOND 160
#define KP_HID  320
#define KP_CAT  448
#define NPAD    320            // output cols padded (2 tiles of 160)

// GEMM tiling
#define BM 128
#define BN 160
#define BK 32
// smem: rows padded to 80 B (40 bf16) for conflict-free ldmatrix
#define A_BYTES  (128 * 80)            // 10240
#define B_BYTES  (160 * 80)            // 12800
#define OFF_ALO  A_BYTES
#define OFF_BHI  (2 * A_BYTES)
#define OFF_BLO  (2 * A_BYTES + B_BYTES)
#define STAGE    (2 * A_BYTES + 2 * B_BYTES)   // 46080
#define SMEM_GEMM (2 * STAGE)                  // 92160

// ---------------------------------------------------------------------------
// Scratch (device globals — no allocation)
// Buffer lifecycle (race-free by construction; each launch reads only buffers
// finalized by earlier launches, except same-element epilogue residual reads):
//   launch 1 (MODE 0):        writes g_inp (raw pre-relu)
//   launch 2 (MODE 1, SRC 0): reads g_inp (gathered, as relu), writes g_msg
//   launch 3 (MODE 1, SRC 1): reads g_msg (gathered), reads g_inp ONLY at its
//                             own output elements (residual), writes g_inp
//                             -> g_inp now holds the iter-2 post-relu message
//   launch 4 (MODE 2):        reads g_amsg (from gather over g_inp), writes g_hid
// ---------------------------------------------------------------------------
__device__ float g_inp [(size_t)N_BONDS * HIDDEN];
__device__ float g_msg [(size_t)N_BONDS * HIDDEN];
__device__ float g_amsg[(size_t)N_ATOMS * HIDDEN];
__device__ float g_hid [(size_t)N_ATOMS * HIDDEN];

__device__ __nv_bfloat16 g_Wi_hi[(size_t)NPAD * KP_BOND];
__device__ __nv_bfloat16 g_Wi_lo[(size_t)NPAD * KP_BOND];
__device__ __nv_bfloat16 g_Wh_hi[(size_t)NPAD * KP_HID];
__device__ __nv_bfloat16 g_Wh_lo[(size_t)NPAD * KP_HID];
__device__ __nv_bfloat16 g_Wo_hi[(size_t)NPAD * KP_CAT];
__device__ __nv_bfloat16 g_Wo_lo[(size_t)NPAD * KP_CAT];

// ---------------------------------------------------------------------------
// PTX helpers (sm_80-era ISA only — harness targets plain sm_100)
// ---------------------------------------------------------------------------
__device__ __forceinline__ uint32_t smem_u32(const void* p) {
    uint32_t a;
    asm("{ .reg .u64 t; cvta.to.shared.u64 t, %1; cvt.u32.u64 %0, t; }"
        : "=r"(a) : "l"(p));
    return a;
}
__device__ __forceinline__ void cpa16(uint32_t d, const void* s) {
    asm volatile("cp.async.cg.shared.global [%0], [%1], 16;" :: "r"(d), "l"(s));
}
#define CP_COMMIT() asm volatile("cp.async.commit_group;" ::: "memory")
#define CP_WAIT0()  asm volatile("cp.async.wait_group 0;" ::: "memory")

__device__ __forceinline__ void ldm4(uint32_t* r, uint32_t addr) {
    asm volatile("ldmatrix.sync.aligned.m8n8.x4.shared.b16 {%0,%1,%2,%3}, [%4];"
                 : "=r"(r[0]), "=r"(r[1]), "=r"(r[2]), "=r"(r[3]) : "r"(addr));
}
__device__ __forceinline__ void mma16816(float* c, const uint32_t* a,
                                         uint32_t b0, uint32_t b1) {
    asm volatile("mma.sync.aligned.m16n8k16.row.col.f32.bf16.bf16.f32 "
                 "{%0,%1,%2,%3}, {%4,%5,%6,%7}, {%8,%9}, {%0,%1,%2,%3};"
                 : "+f"(c[0]), "+f"(c[1]), "+f"(c[2]), "+f"(c[3])
                 : "r"(a[0]), "r"(a[1]), "r"(a[2]), "r"(a[3]), "r"(b0), "r"(b1));
}
__device__ __forceinline__ void split2(float v, __nv_bfloat16& h, __nv_bfloat16& l) {
    h = __float2bfloat16(v);
    l = __float2bfloat16(v - __bfloat162float(h));
}

// ---------------------------------------------------------------------------
// Weight conversion: W[k][300] fp32 -> transposed [NPAD][KP] bf16 hi/lo
// ---------------------------------------------------------------------------
template <int WS>
__global__ __launch_bounds__(256)
void conv_weight(const float* __restrict__ W)
{
    constexpr int K  = (WS == 0) ? BOND_FDIM : (WS == 1) ? HIDDEN : CAT_DIM;
    constexpr int KP = (WS == 0) ? KP_BOND   : (WS == 1) ? KP_HID : KP_CAT;
    __nv_bfloat16* H = (WS == 0) ? g_Wi_hi : (WS == 1) ? g_Wh_hi : g_Wo_hi;
    __nv_bfloat16* L = (WS == 0) ? g_Wi_lo : (WS == 1) ? g_Wh_lo : g_Wo_lo;
    int idx = blockIdx.x * 256 + threadIdx.x;
    if (idx >= NPAD * KP) return;
    int n = idx / KP, k = idx % KP;
    float v = (n < HIDDEN && k < K) ? W[(size_t)k * HIDDEN + n] : 0.f;
    __nv_bfloat16 h, l; split2(v, h, l);
    H[idx] = h; L[idx] = l;
}

// ---------------------------------------------------------------------------
// Atom gather: g_amsg[a] = sum_k msgval(a2b[a,k])
// SRC 0: msgval = relu(g_inp[.])  (g_inp holds raw pre-relu values)
// SRC 1: msgval = g_msg[.]
// SRC 2: msgval = g_inp[.]        (g_inp holds post-relu iter-2 message)
// ---------------------------------------------------------------------------
template <int SRC>
__global__ __launch_bounds__(96)
void atom_gather(const int* __restrict__ a2b)
{
    int a = blockIdx.x, t = threadIdx.x;
    if (t >= 75) return;
    const float4* m4 = (SRC == 1) ? (const float4*)g_msg : (const float4*)g_inp;
    int b0 = a2b[a*MAX_NB+0], b1 = a2b[a*MAX_NB+1], b2 = a2b[a*MAX_NB+2];
    int b3 = a2b[a*MAX_NB+3], b4 = a2b[a*MAX_NB+4], b5 = a2b[a*MAX_NB+5];
    float4 v0 = m4[(size_t)b0*75 + t];
    float4 v1 = m4[(size_t)b1*75 + t]; float4 v2 = m4[(size_t)b2*75 + t];
    float4 v3 = m4[(size_t)b3*75 + t]; float4 v4 = m4[(size_t)b4*75 + t];
    float4 v5 = m4[(size_t)b5*75 + t];
    float4 s;
    if (SRC == 0) {
        s.x = fmaxf(v0.x,0.f)+fmaxf(v1.x,0.f)+fmaxf(v2.x,0.f)+fmaxf(v3.x,0.f)+fmaxf(v4.x,0.f)+fmaxf(v5.x,0.f);
        s.y = fmaxf(v0.y,0.f)+fmaxf(v1.y,0.f)+fmaxf(v2.y,0.f)+fmaxf(v3.y,0.f)+fmaxf(v4.y,0.f)+fmaxf(v5.y,0.f);
        s.z = fmaxf(v0.z,0.f)+fmaxf(v1.z,0.f)+fmaxf(v2.z,0.f)+fmaxf(v3.z,0.f)+fmaxf(v4.z,0.f)+fmaxf(v5.z,0.f);
        s.w = fmaxf(v0.w,0.f)+fmaxf(v1.w,0.f)+fmaxf(v2.w,0.f)+fmaxf(v3.w,0.f)+fmaxf(v4.w,0.f)+fmaxf(v5.w,0.f);
    } else {
        s.x = v0.x+v1.x+v2.x+v3.x+v4.x+v5.x;
        s.y = v0.y+v1.y+v2.y+v3.y+v4.y+v5.y;
        s.z = v0.z+v1.z+v2.z+v3.z+v4.z+v5.z;
        s.w = v0.w+v1.w+v2.w+v3.w+v4.w+v5.w;
    }
    ((float4*)g_amsg)[(size_t)a*75 + t] = s;
}

// ---------------------------------------------------------------------------
// bf16x3 split-float GEMM via mma.sync.
// MODE 0: A = f_bonds (ext)            -> g_inp = A@Wi (raw)
// MODE 1: A[b] = amsg[b2a[b]] - msgval(b2revb[b])   (fused bond_prep)
//         SRC 0: msgval = relu(g_inp), out -> g_msg
//         SRC 1: msgval = g_msg,       out -> g_inp  (residual read is at the
//                same element this block writes; A-load reads g_msg only, so
//                no cross-block race)
// MODE 2: A[a] = [f_atoms | amsg]      -> g_hid = relu(A@Wo + bias)
// ---------------------------------------------------------------------------
template <int MODE, int SRC>
__global__ __launch_bounds__(256)
void mma_gemm(const float* __restrict__ Aext, const float* __restrict__ bias,
              const int* __restrict__ b2a, const int* __restrict__ b2revb)
{
    constexpr int KA = (MODE == 0) ? BOND_FDIM : (MODE == 1) ? HIDDEN : CAT_DIM;
    constexpr int KP = (MODE == 0) ? KP_BOND   : (MODE == 1) ? KP_HID : KP_CAT;
    constexpr int M  = (MODE == 2) ? N_ATOMS : N_BONDS;
    constexpr int NC = KP / BK;

    const __nv_bfloat16* Bh = (MODE == 0) ? g_Wi_hi : (MODE == 1) ? g_Wh_hi : g_Wo_hi;
    const __nv_bfloat16* Bl = (MODE == 0) ? g_Wi_lo : (MODE == 1) ? g_Wh_lo : g_Wo_lo;

    extern __shared__ __align__(128) char smem[];
    const uint32_t sb = smem_u32(smem);
    const int tid = threadIdx.x, lane = tid & 31, wid = tid >> 5;
    const int wm = wid & 3, wn = wid >> 2;
    const int m0 = blockIdx.y * BM, n0 = blockIdx.x * BN;

    float acc[2][10][4];
#pragma unroll
    for (int i = 0; i < 2; i++)
#pragma unroll
        for (int j = 0; j < 10; j++)
#pragma unroll
            for (int k = 0; k < 4; k++) acc[i][j][k] = 0.f;

    float areg[16];

#define LOAD_A(cc) do { \
    int _c = (cc); \
    _Pragma("unroll") \
    for (int i = 0; i < 16; i++) { \
        int idx = i * 256 + tid; \
        int row = idx >> 5, col = idx & 31; \
        int gm = m0 + row, gk = _c * BK + col; \
        float v = 0.f; \
        if (gm < M && gk < KA) { \
            if (MODE == 0) { \
                v = Aext[(size_t)gm * BOND_FDIM + gk]; \
            } else if (MODE == 1) { \
                int a  = __ldg(&b2a[gm]); \
                int rb = __ldg(&b2revb[gm]); \
                float x = g_amsg[(size_t)a * HIDDEN + gk]; \
                float y = (SRC == 0) ? fmaxf(g_inp[(size_t)rb * HIDDEN + gk], 0.f) \
                                     : g_msg[(size_t)rb * HIDDEN + gk]; \
                v = x - y; \
            } else { \
                v = (gk < ATOM_FDIM) ? Aext[(size_t)gm * ATOM_FDIM + gk] \
                                     : g_amsg[(size_t)gm * HIDDEN + (gk - ATOM_FDIM)]; \
            } \
        } \
        areg[i] = v; \
    } } while (0)

#define STS_A(cc) do { \
    char* st = smem + ((cc) & 1) * STAGE; \
    _Pragma("unroll") \
    for (int i = 0; i < 16; i++) { \
        int idx = i * 256 + tid; \
        int row = idx >> 5, col = idx & 31; \
        __nv_bfloat16 h, l; split2(areg[i], h, l); \
        *(__nv_bfloat16*)(st + row * 80 + col * 2) = h; \
        *(__nv_bfloat16*)(st + OFF_ALO + row * 80 + col * 2) = l; \
    } } while (0)

#define LOAD_B(cc) do { \
    int _c = (cc); \
    uint32_t dh = sb + (_c & 1) * STAGE + OFF_BHI; \
    uint32_t dl = sb + (_c & 1) * STAGE + OFF_BLO; \
    _Pragma("unroll") \
    for (int i = 0; i < 3; i++) { \
        int idx = i * 256 + tid; \
        if (idx < 640) { \
            int row = idx >> 2, ch = idx & 3; \
            size_t g = (size_t)(n0 + row) * KP + _c * BK + ch * 8; \
            cpa16(dh + row * 80 + ch * 16, Bh + g); \
            cpa16(dl + row * 80 + ch * 16, Bl + g); \
        } \
    } } while (0)

    // prologue
    LOAD_A(0); LOAD_B(0); CP_COMMIT(); STS_A(0); CP_WAIT0(); __syncthreads();

    for (int c = 0; c < NC; c++) {
        const bool has_next = (c + 1 < NC);
        if (has_next) { LOAD_A(c + 1); LOAD_B(c + 1); CP_COMMIT(); }

        const uint32_t sA = sb + (c & 1) * STAGE;
#pragma unroll
        for (int ks = 0; ks < 2; ks++) {
            uint32_t ah[2][4], al[2][4];
#pragma unroll
            for (int mi = 0; mi < 2; mi++) {
                int row = wm * 32 + mi * 16 + (lane & 15);
                uint32_t ad = sA + row * 80 + ks * 32 + (lane >> 4) * 16;
                ldm4(ah[mi], ad);
                ldm4(al[mi], ad + OFF_ALO);
            }
            uint32_t bh[5][4], bl[5][4];
            {
                int g = lane >> 3, w = lane & 7;
                int rofs = ((g & 2) ? 8 : 0) + w;
                int cofs = ks * 32 + (g & 1) * 16;
#pragma unroll
                for (int nj = 0; nj < 5; nj++) {
                    int row = wn * 80 + nj * 16 + rofs;
                    uint32_t bd = sA + OFF_BHI + row * 80 + cofs;
                    ldm4(bh[nj], bd);
                    ldm4(bl[nj], bd + (OFF_BLO - OFF_BHI));
                }
            }
#pragma unroll
            for (int mi = 0; mi < 2; mi++)
#pragma unroll
                for (int nj = 0; nj < 5; nj++) {
                    mma16816(acc[mi][2*nj],   ah[mi], bh[nj][0], bh[nj][1]);
                    mma16816(acc[mi][2*nj],   ah[mi], bl[nj][0], bl[nj][1]);
                    mma16816(acc[mi][2*nj],   al[mi], bh[nj][0], bh[nj][1]);
                    mma16816(acc[mi][2*nj+1], ah[mi], bh[nj][2], bh[nj][3]);
                    mma16816(acc[mi][2*nj+1], ah[mi], bl[nj][2], bl[nj][3]);
                    mma16816(acc[mi][2*nj+1], al[mi], bh[nj][2], bh[nj][3]);
                }
        }

        if (has_next) { STS_A(c + 1); CP_WAIT0(); __syncthreads(); }
    }

    // epilogue
    const int r_base = m0 + wm * 32 + (lane >> 2);
    const int c_base = n0 + wn * 80 + (lane & 3) * 2;
#pragma unroll
    for (int mi = 0; mi < 2; mi++)
#pragma unroll
        for (int nf = 0; nf < 10; nf++) {
            int gc = c_base + nf * 8;
#pragma unroll
            for (int h = 0; h < 2; h++) {
                int r = r_base + mi * 16 + h * 8;
                if (r >= M) continue;
#pragma unroll
                for (int q = 0; q < 2; q++) {
                    int cc = gc + q;
                    if (cc >= HIDDEN) continue;
                    float v = acc[mi][nf][h * 2 + q];
                    size_t o = (size_t)r * HIDDEN + cc;
                    if (MODE == 0) {
                        g_inp[o] = v;
                    } else if (MODE == 1) {
                        float rv = fmaxf(v + g_inp[o], 0.f);
                        if (SRC == 0) g_msg[o] = rv; else g_inp[o] = rv;
                    } else {
                        g_hid[o] = fmaxf(v + bias[cc], 0.f);
                    }
                }
            }
        }
#undef LOAD_A
#undef STS_A
#undef LOAD_B
}

// ---------------------------------------------------------------------------
// Mean pool per molecule (a2mol sorted)
// ---------------------------------------------------------------------------
__global__ __launch_bounds__(128)
void pool_kernel(const int* __restrict__ a2mol, float* __restrict__ out)
{
    const int m = blockIdx.x;
    int lo = 0, hi = N_ATOMS;
    while (lo < hi) { int mid = (lo + hi) >> 1; if (a2mol[mid] <  m) lo = mid + 1; else hi = mid; }
    const int start = lo;
    hi = N_ATOMS;
    while (lo < hi) { int mid = (lo + hi) >> 1; if (a2mol[mid] <= m) lo = mid + 1; else hi = mid; }
    const int end = lo;
    const float inv = (end > start) ? 1.f / (float)(end - start) : 0.f;
    for (int c = threadIdx.x; c < HIDDEN; c += 128) {
        float s = 0.f;
        for (int a = start; a < end; a++) s += g_hid[(size_t)a * HIDDEN + c];
        out[(size_t)m * HIDDEN + c] = s * inv;
    }
}

// ---------------------------------------------------------------------------
// Launch
// ---------------------------------------------------------------------------
extern "C" void kernel_launch(void* const* d_in, const int* in_sizes, int n_in,
                              void* d_out, int out_size)
{
    const float* f_atoms = (const float*)d_in[0];
    const float* f_bonds = (const float*)d_in[1];
    const int*   a2b     = (const int*)  d_in[2];
    const int*   b2a     = (const int*)  d_in[3];
    const int*   b2revb  = (const int*)  d_in[4];
    const int*   a2mol   = (const int*)  d_in[5];
    int wbase = 6;
    if (n_in >= 11 && in_sizes[6] == 1) wbase = 7;
    const float* W_i = (const float*)d_in[wbase + 0];
    const float* W_h = (const float*)d_in[wbase + 1];
    const float* W_o = (const float*)d_in[wbase + 2];
    const float* b_o = (const float*)d_in[wbase + 3];
    float* out = (float*)d_out;

    cudaFuncSetAttribute(mma_gemm<0,0>, cudaFuncAttributeMaxDynamicSharedMemorySize, SMEM_GEMM);
    cudaFuncSetAttribute(mma_gemm<1,0>, cudaFuncAttributeMaxDynamicSharedMemorySize, SMEM_GEMM);
    cudaFuncSetAttribute(mma_gemm<1,1>, cudaFuncAttributeMaxDynamicSharedMemorySize, SMEM_GEMM);
    cudaFuncSetAttribute(mma_gemm<2,1>, cudaFuncAttributeMaxDynamicSharedMemorySize, SMEM_GEMM);

    // weight conversions (tiny)
    conv_weight<0><<<(NPAD*KP_BOND + 255)/256, 256>>>(W_i);
    conv_weight<1><<<(NPAD*KP_HID  + 255)/256, 256>>>(W_h);
    conv_weight<2><<<(NPAD*KP_CAT  + 255)/256, 256>>>(W_o);

    const dim3 grid_b(2, (N_BONDS + BM - 1) / BM);
    const dim3 grid_a(2, (N_ATOMS + BM - 1) / BM);

    // 1) g_inp = f_bonds @ W_i (raw; message implied as relu(g_inp))
    mma_gemm<0,0><<<grid_b, 256, SMEM_GEMM>>>(f_bonds, nullptr, nullptr, nullptr);

    // 2) iter 1: gather relu(g_inp); GEMM reads g_inp (gathered), writes g_msg
    atom_gather<0><<<N_ATOMS, 96>>>(a2b);
    mma_gemm<1,0><<<grid_b, 256, SMEM_GEMM>>>(nullptr, nullptr, b2a, b2revb);

    //    iter 2: gather g_msg; GEMM reads g_msg (gathered), writes g_inp
    atom_gather<1><<<N_ATOMS, 96>>>(a2b);
    mma_gemm<1,1><<<grid_b, 256, SMEM_GEMM>>>(nullptr, nullptr, b2a, b2revb);

    // 3) final gather from g_inp (post-relu message) + fused-concat readout
    atom_gather<2><<<N_ATOMS, 96>>>(a2b);
    mma_gemm<2,1><<<grid_a, 256, SMEM_GEMM>>>(f_atoms, b_o, b2a, b2revb);

    // 4) pool
    pool_kernel<<<N_MOLS_C, 128>>>(a2mol, out);
}